// round 15
// baseline (speedup 1.0000x reference)
#include <cuda_runtime.h>
#include <cuda_bf16.h>
#include <mma.h>
#include <math.h>
#include <stdint.h>

using namespace nvcuda;

// Problem constants
constexpr int NB   = 16384;
constexpr int NF   = 18;
constexpr int NE   = 64;
constexpr int IN0  = 1152;
constexpr int D1   = 512;
constexpr int D2   = 256;
constexpr int NVOC = 100000;

// ---------------- static device scratch ----------------
__device__ __align__(1024) __nv_bfloat16 d_featb[(size_t)NB*IN0];   // bf16 features
__device__ __align__(1024) float d_h0   [(size_t)12*NB*D1];         // f32 expert out
__device__ __align__(1024) float d_h1   [(size_t)16*NB*D2];         // f32 expert out
__device__ __align__(1024) __nv_bfloat16 d_fea1b[(size_t)2*NB*D1];  // bf16 combined
__device__ __align__(1024) __nv_bfloat16 d_fea2b[(size_t)2*NB*D2];  // bf16 combined
__device__ __align__(1024) __nv_bfloat16 d_w0b[(size_t)12*IN0*D1];
__device__ __align__(1024) __nv_bfloat16 d_w1b[(size_t)12*D1*D2];
__device__ __align__(1024) __nv_bfloat16 d_tw0b[(size_t)2*D2*128];
__device__ __align__(1024) __nv_bfloat16 d_tw1b[(size_t)2*128*64];
__device__ float d_t1raw[(size_t)2*NB*128];
__device__ __align__(1024) __nv_bfloat16 d_t1b[(size_t)2*NB*128];
__device__ float d_t2raw[(size_t)2*NB*64];
__device__ float d_gate0[(size_t)NB*16];
__device__ float d_gate1[(size_t)NB*16];

__device__ float d_sum0[12*D1], d_sq0[12*D1], d_a0[12*D1], d_c0[12*D1];
__device__ float d_sum1[16*D2], d_sq1[16*D2], d_a1[16*D2], d_c1[16*D2];
__device__ float d_sumT0[2*128], d_sqT0[2*128], d_aT0[2*128], d_cT0[2*128];
__device__ float d_sumT1[2*64],  d_sqT1[2*64],  d_aT1[2*64],  d_cT1[2*64];

__device__ __forceinline__ int expert_of(int z){
  int t = z >> 3, k = z & 7;
  return (k < 4) ? (t*4 + k) : (4 + k);
}

__device__ __forceinline__ void st_bf16x4(__nv_bfloat16* p, float4 v){
  __nv_bfloat162 lo = __floats2bfloat162_rn(v.x, v.y);
  __nv_bfloat162 hi = __floats2bfloat162_rn(v.z, v.w);
  uint2 u; u.x = *(unsigned*)&lo; u.y = *(unsigned*)&hi;
  *(uint2*)p = u;
}

// ---------------- cp.async helpers ----------------
__device__ __forceinline__ uint32_t smem_u32(const void* p){
  uint32_t a;
  asm("{ .reg .u64 t; cvta.to.shared.u64 t, %1; cvt.u32.u64 %0, t; }" : "=r"(a) : "l"(p));
  return a;
}
__device__ __forceinline__ void cp16(uint32_t s, const void* g){
  asm volatile("cp.async.cg.shared.global [%0], [%1], 16;" :: "r"(s), "l"(g) : "memory");
}
#define CP_COMMIT() asm volatile("cp.async.commit_group;" ::: "memory")
#define CP_WAIT(n)  asm volatile("cp.async.wait_group %0;" :: "n"(n) : "memory")

// ---------------- bf16 wmma grouped GEMM, templated on MODE (R12) ----------------
constexpr int BM = 128, BKb = 64;
constexpr int S_STG = 3;
constexpr int A_LDb = 72;
constexpr int B_LDb = 136;
constexpr int A_STG_B = BM * A_LDb * 2;
constexpr int B_STG_B = BKb * B_LDb * 2;
constexpr int STG_B   = A_STG_B + B_STG_B;     // 35840
constexpr int SMEM_GB = S_STG * STG_B;         // 107520

typedef wmma::fragment<wmma::matrix_a, 16,16,16, __nv_bfloat16, wmma::row_major> FA;
typedef wmma::fragment<wmma::matrix_b, 16,16,16, __nv_bfloat16, wmma::row_major> FB;
typedef wmma::fragment<wmma::accumulator, 16,16,16, float> FC;

template<int MODE>
__global__ void __launch_bounds__(128,2) bf16_gemm_kernel(const __nv_bfloat16* __restrict__ w0,
                                                          const __nv_bfloat16* __restrict__ w1){
  constexpr int N  = (MODE==0) ? D1 : (MODE==1) ? D2 : (MODE==2) ? 128 : 64;
  constexpr int K  = (MODE==0) ? IN0 : (MODE==1) ? D1 : (MODE==2) ? D2 : 128;
  constexpr int NK = K / BKb;

  extern __shared__ char sm[];
  const uint32_t sb = smem_u32(sm);
  const int tid = threadIdx.x;
  const int wid = tid >> 5;
  const int wm = wid >> 1;
  const int wn = wid & 1;

  const int z = blockIdx.z;
  const __nv_bfloat16* A; const __nv_bfloat16* W; float* C;
  float* sumP; float* sqP;
  if(MODE == 0){
    A = d_featb;
    W = w0 + (size_t)z*K*N;
    C = d_h0 + (size_t)z*NB*N;
    sumP = d_sum0 + z*N; sqP = d_sq0 + z*N;
  } else if(MODE == 1){
    int t = z >> 3, e = expert_of(z);
    A = d_fea1b + (size_t)t*NB*D1;
    W = w1 + (size_t)e*K*N;
    C = d_h1 + (size_t)z*NB*N;
    sumP = d_sum1 + z*N; sqP = d_sq1 + z*N;
  } else if(MODE == 2){
    A = d_fea2b + (size_t)z*NB*D2;
    W = d_tw0b + (size_t)z*K*N;
    C = d_t1raw + (size_t)z*NB*N;
    sumP = d_sumT0 + z*N; sqP = d_sqT0 + z*N;
  } else {
    A = d_t1b + (size_t)z*NB*128;
    W = d_tw1b + (size_t)z*K*N;
    C = d_t2raw + (size_t)z*NB*N;
    sumP = d_sumT1 + z*N; sqP = d_sqT1 + z*N;
  }
  const int m0 = blockIdx.y * BM;
  const int n0 = blockIdx.x * 128;

  // For N<128: zero-fill the never-written B smem columns once.
  if(N < 128){
    for(int i = tid; i < S_STG*B_STG_B/4; i += 128)
      ((uint32_t*)(sm))[ (A_STG_B/4) + (i/(B_STG_B/4))*(STG_B/4) + (i % (B_STG_B/4)) ] = 0;
    __syncthreads();
  }

  const __nv_bfloat16* Abase = A + (size_t)m0 * K;
  const __nv_bfloat16* Bbase = W + n0;

  auto load_stage = [&](int kc, int buf){
    const __nv_bfloat16* gA = Abase + (size_t)kc * BKb;
    const __nv_bfloat16* gB = Bbase + (size_t)kc * BKb * N;
    uint32_t sA = sb + buf * STG_B;
    uint32_t sB = sA + A_STG_B;
    #pragma unroll
    for(int it = 0; it < 8; ++it){
      int idx = it*128 + tid;
      int r = idx >> 3, q = idx & 7;
      cp16(sA + (uint32_t)(r*A_LDb + q*8)*2, gA + (size_t)r*K + q*8);
    }
    #pragma unroll
    for(int it = 0; it < 8; ++it){
      int idx = it*128 + tid;
      int r = idx >> 4, q = idx & 15;
      if(N >= 128 || q*8 < N)
        cp16(sB + (uint32_t)(r*B_LDb + q*8)*2, gB + (size_t)r*N + q*8);
    }
  };

  FC acc[4][4];
  #pragma unroll
  for(int i = 0; i < 4; ++i)
    #pragma unroll
    for(int j = 0; j < 4; ++j) wmma::fill_fragment(acc[i][j], 0.f);

  load_stage(0, 0); CP_COMMIT();
  load_stage(1, 1); CP_COMMIT();

  for(int kc = 0; kc < NK; ++kc){
    CP_WAIT(1);
    __syncthreads();
    int ts = kc + 2;
    if(ts < NK) load_stage(ts, ts % S_STG);
    CP_COMMIT();
    const __nv_bfloat16* As = (const __nv_bfloat16*)(sm + (kc % S_STG) * STG_B);
    const __nv_bfloat16* Bs = (const __nv_bfloat16*)(sm + (kc % S_STG) * STG_B + A_STG_B);
    #pragma unroll
    for(int ks = 0; ks < 4; ++ks){
      FB b[4];
      #pragma unroll
      for(int jn = 0; jn < 4; ++jn)
        wmma::load_matrix_sync(b[jn], Bs + (ks*16)*B_LDb + wn*64 + jn*16, B_LDb);
      #pragma unroll
      for(int im = 0; im < 4; ++im){
        FA a;
        wmma::load_matrix_sync(a, As + (wm*64 + im*16)*A_LDb + ks*16, A_LDb);
        #pragma unroll
        for(int jn = 0; jn < 4; ++jn)
          wmma::mma_sync(acc[im][jn], a, b[jn], acc[im][jn]);
      }
    }
  }
  __syncthreads();

  // ---- epilogue: frags -> smem(f32) -> coalesced f32 gmem + fused BN stats ----
  float* shf = (float*)sm;     // 128 x 132
  #pragma unroll
  for(int im = 0; im < 4; ++im)
    #pragma unroll
    for(int jn = 0; jn < 4; ++jn)
      wmma::store_matrix_sync(shf + (wm*64 + im*16)*132 + wn*64 + jn*16,
                              acc[im][jn], 132, wmma::mem_row_major);
  __syncthreads();

  float* Crow = C + (size_t)m0*N + n0;
  #pragma unroll 4
  for(int it = 0; it < 32; ++it){
    int idx = it*128 + tid;
    int row = idx >> 5, q = (idx & 31)*4;
    if(N >= 128 || q < N){
      float4 v = make_float4(shf[row*132+q], shf[row*132+q+1],
                             shf[row*132+q+2], shf[row*132+q+3]);
      *(float4*)(Crow + (size_t)row*N + q) = v;
    }
  }
  {
    int col = tid;
    if(N >= 128 || col < N){
      float s = 0.f, q = 0.f;
      #pragma unroll 8
      for(int r = 0; r < 128; ++r){
        float v = shf[r*132 + col]; s += v; q += v*v;
      }
      atomicAdd(&sumP[n0 + col], s);
      atomicAdd(&sqP[n0 + col], q);
    }
  }
}

// f32 -> bf16 conversion (weights), float4-vectorized
__global__ void conv_bf16_kernel(const float* __restrict__ src, __nv_bfloat16* __restrict__ dst, int n4){
  int i = blockIdx.x*blockDim.x + threadIdx.x;
  if(i >= n4) return;
  float4 v = *(const float4*)(src + (size_t)i*4);
  st_bf16x4(dst + (size_t)i*4, v);
}

// ---------------- small kernels ----------------
__global__ void zero_stats_kernel(){
  int i = blockIdx.x*blockDim.x + threadIdx.x;
  if(i < 12*D1){ d_sum0[i]=0.f; d_sq0[i]=0.f; }
  if(i < 16*D2){ d_sum1[i]=0.f; d_sq1[i]=0.f; }
  if(i < 2*128){ d_sumT0[i]=0.f; d_sqT0[i]=0.f; }
  if(i < 2*64 ){ d_sumT1[i]=0.f; d_sqT1[i]=0.f; }
}

// gather -> bf16 features only
__global__ void gather_kernel(const int* __restrict__ x, const float* __restrict__ emb){
  int idx = blockIdx.x*blockDim.x + threadIdx.x;   // NB*NF*16
  int q = idx & 15;
  int f = (idx >> 4) % NF;
  int b = idx / (16*NF);
  int v = x[b*NF + f];
  float4 val = *(const float4*)(emb + ((size_t)f*NVOC + (size_t)v)*NE + q*4);
  st_bf16x4(d_featb + (size_t)b*IN0 + f*NE + q*4, val);
}

__device__ __forceinline__ void warp_reduce16(float* acc){
  #pragma unroll
  for(int off=16; off; off>>=1)
    #pragma unroll
    for(int j=0;j<16;j++) acc[j] += __shfl_xor_sync(0xffffffffu, acc[j], off);
}
__device__ __forceinline__ void softmax8(const float* l, float* o){
  float m = l[0];
  #pragma unroll
  for(int j=1;j<8;j++) m = fmaxf(m, l[j]);
  float s = 0.f, e[8];
  #pragma unroll
  for(int j=0;j<8;j++){ e[j] = expf(l[j]-m); s += e[j]; }
  float inv = 1.f/s;
  #pragma unroll
  for(int j=0;j<8;j++) o[j] = e[j]*inv;
}

// gate0 from bf16 features (R11 version — runs on s1, hidden under GEMM0)
__global__ void gate0_kernel(const float* __restrict__ gw, const float* __restrict__ gb){
  int w = (blockIdx.x*blockDim.x + threadIdx.x) >> 5;
  int lane = threadIdx.x & 31;
  if(w >= NB) return;
  const __nv_bfloat16* frow = d_featb + (size_t)w*IN0;
  float acc[16];
  #pragma unroll
  for(int j=0;j<16;j++) acc[j]=0.f;
  for(int k2 = lane; k2 < IN0/2; k2 += 32){
    float2 f2 = __bfloat1622float2(*(const __nv_bfloat162*)(frow + 2*k2));
    int k = 2*k2;
    const float* g0a = gw + k*8;
    const float* g1a = gw + IN0*8 + k*8;
    #pragma unroll
    for(int j=0;j<8;j++){
      acc[j]   += f2.x*g0a[j] + f2.y*g0a[8+j];
      acc[8+j] += f2.x*g1a[j] + f2.y*g1a[8+j];
    }
  }
  warp_reduce16(acc);
  if(lane==0){
    float l[8], o[8];
    #pragma unroll
    for(int t=0;t<2;t++){
      #pragma unroll
      for(int j=0;j<8;j++) l[j] = acc[t*8+j] + gb[t*8+j];
      softmax8(l,o);
      #pragma unroll
      for(int j=0;j<8;j++) d_gate0[(size_t)w*16 + t*8 + j] = o[j];
    }
  }
}

// gate1 from bf16 fea1 (R11 version — runs on s1, hidden under GEMM1)
__global__ void gate1_kernel(const float* __restrict__ gw, const float* __restrict__ gb){
  int w = (blockIdx.x*blockDim.x + threadIdx.x) >> 5;
  int lane = threadIdx.x & 31;
  if(w >= NB) return;
  const __nv_bfloat16* f0 = d_fea1b + (size_t)w*D1;
  const __nv_bfloat16* f1 = d_fea1b + (size_t)NB*D1 + (size_t)w*D1;
  float acc[16];
  #pragma unroll
  for(int j=0;j<16;j++) acc[j]=0.f;
  for(int k2 = lane; k2 < D1/2; k2 += 32){
    float2 a2 = __bfloat1622float2(*(const __nv_bfloat162*)(f0 + 2*k2));
    float2 b2 = __bfloat1622float2(*(const __nv_bfloat162*)(f1 + 2*k2));
    int k = 2*k2;
    const float* g0a = gw + k*8;
    const float* g1a = gw + D1*8 + k*8;
    #pragma unroll
    for(int j=0;j<8;j++){
      acc[j]   += a2.x*g0a[j] + a2.y*g0a[8+j];
      acc[8+j] += b2.x*g1a[j] + b2.y*g1a[8+j];
    }
  }
  warp_reduce16(acc);
  if(lane==0){
    float l[8], o[8];
    #pragma unroll
    for(int t=0;t<2;t++){
      #pragma unroll
      for(int j=0;j<8;j++) l[j] = acc[t*8+j] + gb[t*8+j];
      softmax8(l,o);
      #pragma unroll
      for(int j=0;j<8;j++) d_gate1[(size_t)w*16 + t*8 + j] = o[j];
    }
  }
}

__global__ void finalize_kernel(int mode, const float* __restrict__ g, const float* __restrict__ bt){
  int i = blockIdx.x*blockDim.x + threadIdx.x;
  const float* sum; const float* sq; float* a; float* c; int N, NZ;
  if(mode==0){ sum=d_sum0; sq=d_sq0; a=d_a0; c=d_c0; N=D1; NZ=12; }
  else if(mode==1){ sum=d_sum1; sq=d_sq1; a=d_a1; c=d_c1; N=D2; NZ=16; }
  else if(mode==2){ sum=d_sumT0; sq=d_sqT0; a=d_aT0; c=d_cT0; N=128; NZ=2; }
  else { sum=d_sumT1; sq=d_sqT1; a=d_aT1; c=d_cT1; N=64; NZ=2; }
  if(i >= NZ*N) return;
  int z = i / N, o = i - z*N;
  int gz = (mode==1) ? expert_of(z) : z;
  float mu  = sum[i] * (1.f/NB);
  float var = sq[i] * (1.f/NB) - mu*mu;
  float aa  = g[gz*N+o] * rsqrtf(var + 1e-5f);
  a[i] = aa;
  c[i] = bt[gz*N+o] - mu*aa;
}

// combine0: f32 h0 (R12 path), BN+relu, gate sums -> bf16 fea1b only
__global__ void combine0_kernel(){
  int idx = blockIdx.x*blockDim.x + threadIdx.x;   // NB*128
  int o4 = (idx & 127)*4;
  size_t b = (size_t)(idx >> 7);
  const float* g = d_gate0 + b*16;
  float4 acc0 = make_float4(0,0,0,0), acc1 = make_float4(0,0,0,0);
  #pragma unroll
  for(int e=0;e<12;e++){
    float4 h = *(const float4*)(d_h0 + ((size_t)e*NB + b)*D1 + o4);
    float4 a = *(const float4*)(d_a0 + e*D1 + o4);
    float4 c = *(const float4*)(d_c0 + e*D1 + o4);
    float4 y;
    y.x = fmaxf(h.x*a.x + c.x, 0.f);
    y.y = fmaxf(h.y*a.y + c.y, 0.f);
    y.z = fmaxf(h.z*a.z + c.z, 0.f);
    y.w = fmaxf(h.w*a.w + c.w, 0.f);
    float g0 = (e < 4) ? g[e] : ((e >= 8) ? g[e-4] : 0.f);
    float g1 = (e >= 4) ? g[8 + e - 4] : 0.f;
    acc0.x += g0*y.x; acc0.y += g0*y.y; acc0.z += g0*y.z; acc0.w += g0*y.w;
    acc1.x += g1*y.x; acc1.y += g1*y.y; acc1.z += g1*y.z; acc1.w += g1*y.w;
  }
  st_bf16x4(d_fea1b + b*D1 + o4, acc0);
  st_bf16x4(d_fea1b + (size_t)NB*D1 + b*D1 + o4, acc1);
}

// combine1: f32 h1 -> bf16 fea2b (R12 path)
__global__ void combine1_kernel(){
  int idx = blockIdx.x*blockDim.x + threadIdx.x;   // NB*64
  int o4 = (idx & 63)*4;
  size_t b = (size_t)(idx >> 6);
  const float* g = d_gate1 + b*16;
  float4 acc0 = make_float4(0,0,0,0), acc1 = make_float4(0,0,0,0);
  #pragma unroll
  for(int s=0;s<16;s++){
    float4 h = *(const float4*)(d_h1 + ((size_t)s*NB + b)*D2 + o4);
    float4 a = *(const float4*)(d_a1 + s*D2 + o4);
    float4 c = *(const float4*)(d_c1 + s*D2 + o4);
    float4 y;
    y.x = fmaxf(h.x*a.x + c.x, 0.f);
    y.y = fmaxf(h.y*a.y + c.y, 0.f);
    y.z = fmaxf(h.z*a.z + c.z, 0.f);
    y.w = fmaxf(h.w*a.w + c.w, 0.f);
    float gv = g[s];
    if(s < 8){ acc0.x += gv*y.x; acc0.y += gv*y.y; acc0.z += gv*y.z; acc0.w += gv*y.w; }
    else     { acc1.x += gv*y.x; acc1.y += gv*y.y; acc1.z += gv*y.z; acc1.w += gv*y.w; }
  }
  st_bf16x4(d_fea2b + b*D2 + o4, acc0);
  st_bf16x4(d_fea2b + (size_t)NB*D2 + b*D2 + o4, acc1);
}

// tower BN1 + relu -> bf16 t1
__global__ void normrelu_b_kernel(){
  int i = blockIdx.x*blockDim.x + threadIdx.x;   // 2*NB*32
  if(i >= 2*NB*32) return;
  int o4 = (i & 31)*4;
  int row = i >> 5;
  int t = row / NB;
  float4 h = *(const float4*)(d_t1raw + (size_t)row*128 + o4);
  const float* a = d_aT0 + t*128 + o4;
  const float* c = d_cT0 + t*128 + o4;
  float4 y;
  y.x = fmaxf(h.x*a[0] + c[0], 0.f);
  y.y = fmaxf(h.y*a[1] + c[1], 0.f);
  y.z = fmaxf(h.z*a[2] + c[2], 0.f);
  y.w = fmaxf(h.w*a[3] + c[3], 0.f);
  st_bf16x4(d_t1b + (size_t)row*128 + o4, y);
}

// final: tower BN2 + relu inline on t2raw, then dot + sigmoid
__global__ void final_kernel(const float* __restrict__ tow, const float* __restrict__ tob,
                             float* __restrict__ out){
  int w = (blockIdx.x*blockDim.x + threadIdx.x) >> 5;
  int lane = threadIdx.x & 31;
  if(w >= NB) return;
  size_t b = (size_t)w;
  float v0a = fmaxf(d_t2raw[b*64 + lane]*d_aT1[lane] + d_cT1[lane], 0.f);
  float v0b = fmaxf(d_t2raw[b*64 + lane + 32]*d_aT1[lane + 32] + d_cT1[lane + 32], 0.f);
  float v1a = fmaxf(d_t2raw[(size_t)NB*64 + b*64 + lane]*d_aT1[64 + lane] + d_cT1[64 + lane], 0.f);
  float v1b = fmaxf(d_t2raw[(size_t)NB*64 + b*64 + lane + 32]*d_aT1[64 + lane + 32] + d_cT1[64 + lane + 32], 0.f);
  float s0 = v0a*tow[lane] + v0b*tow[lane + 32];
  float s1 = v1a*tow[64 + lane] + v1b*tow[64 + lane + 32];
  #pragma unroll
  for(int off=16; off; off>>=1){
    s0 += __shfl_xor_sync(0xffffffffu, s0, off);
    s1 += __shfl_xor_sync(0xffffffffu, s1, off);
  }
  if(lane==0){
    out[b]      = 1.f/(1.f + expf(-(s0 + tob[0])));
    out[NB + b] = 1.f/(1.f + expf(-(s1 + tob[1])));
  }
}

// ---------------- host launcher ----------------
extern "C" void kernel_launch(void* const* d_in, const int* in_sizes, int n_in,
                              void* d_out, int out_size){
  const int*   x    = (const int*)  d_in[0];
  const float* emb  = (const float*)d_in[1];
  const float* ew0  = (const float*)d_in[2];
  const float* eg0  = (const float*)d_in[4];
  const float* ebt0 = (const float*)d_in[5];
  const float* gw0  = (const float*)d_in[6];
  const float* gb0  = (const float*)d_in[7];
  const float* ew1  = (const float*)d_in[10];
  const float* eg1  = (const float*)d_in[12];
  const float* ebt1 = (const float*)d_in[13];
  const float* gw1  = (const float*)d_in[14];
  const float* gb1  = (const float*)d_in[15];
  const float* tw0  = (const float*)d_in[18];
  const float* tg0  = (const float*)d_in[20];
  const float* tbt0 = (const float*)d_in[21];
  const float* tw1  = (const float*)d_in[22];
  const float* tg1  = (const float*)d_in[24];
  const float* tbt1 = (const float*)d_in[25];
  const float* tow  = (const float*)d_in[26];
  const float* tob  = (const float*)d_in[27];
  float* out = (float*)d_out;

  static bool init_done = false;
  static cudaStream_t s1 = nullptr;
  static cudaEvent_t evRoot, evConv, evG, evGate0, evC0, evGate1;
  if(!init_done){
    cudaFuncSetAttribute(bf16_gemm_kernel<0>, cudaFuncAttributeMaxDynamicSharedMemorySize, SMEM_GB);
    cudaFuncSetAttribute(bf16_gemm_kernel<1>, cudaFuncAttributeMaxDynamicSharedMemorySize, SMEM_GB);
    cudaFuncSetAttribute(bf16_gemm_kernel<2>, cudaFuncAttributeMaxDynamicSharedMemorySize, SMEM_GB);
    cudaFuncSetAttribute(bf16_gemm_kernel<3>, cudaFuncAttributeMaxDynamicSharedMemorySize, SMEM_GB);
    cudaStreamCreateWithFlags(&s1, cudaStreamNonBlocking);
    cudaEventCreateWithFlags(&evRoot,  cudaEventDisableTiming);
    cudaEventCreateWithFlags(&evConv,  cudaEventDisableTiming);
    cudaEventCreateWithFlags(&evG,     cudaEventDisableTiming);
    cudaEventCreateWithFlags(&evGate0, cudaEventDisableTiming);
    cudaEventCreateWithFlags(&evC0,    cudaEventDisableTiming);
    cudaEventCreateWithFlags(&evGate1, cudaEventDisableTiming);
    init_done = true;
  }

  __nv_bfloat16* w0b;  cudaGetSymbolAddress((void**)&w0b,  d_w0b);
  __nv_bfloat16* w1b;  cudaGetSymbolAddress((void**)&w1b,  d_w1b);
  __nv_bfloat16* tw0b; cudaGetSymbolAddress((void**)&tw0b, d_tw0b);
  __nv_bfloat16* tw1b; cudaGetSymbolAddress((void**)&tw1b, d_tw1b);

  // fork side stream from capture stream
  cudaEventRecord(evRoot, 0);
  cudaStreamWaitEvent(s1, evRoot, 0);

  // s1: zero stats + all weight conversions (independent of gather)
  zero_stats_kernel<<<(12*D1 + 255)/256, 256, 0, s1>>>();
  conv_bf16_kernel<<<(12*IN0*D1/4 + 255)/256, 256, 0, s1>>>(ew0, w0b, 12*IN0*D1/4);
  conv_bf16_kernel<<<(12*D1*D2/4 + 255)/256, 256, 0, s1>>>(ew1, w1b, 12*D1*D2/4);
  conv_bf16_kernel<<<(2*D2*128/4 + 255)/256, 256, 0, s1>>>(tw0, tw0b, 2*D2*128/4);
  conv_bf16_kernel<<<(2*128*64/4 + 255)/256, 256, 0, s1>>>(tw1, tw1b, 2*128*64/4);
  cudaEventRecord(evConv, s1);

  // s0: gather
  gather_kernel<<<(NB*NF*16)/256, 256>>>(x, emb);
  cudaEventRecord(evG, 0);

  // s1: gate0 (needs gather) — overlaps GEMM0 on s0
  cudaStreamWaitEvent(s1, evG, 0);
  gate0_kernel<<<(NB*32)/256, 256, 0, s1>>>(gw0, gb0);
  cudaEventRecord(evGate0, s1);

  // s0: GEMM0 (needs conv + zero)
  cudaStreamWaitEvent(0, evConv, 0);
  bf16_gemm_kernel<0><<<dim3(D1/128, NB/BM, 12), 128, SMEM_GB>>>(w0b, w1b);
  finalize_kernel<<<(12*D1 + 255)/256, 256>>>(0, eg0, ebt0);
  cudaStreamWaitEvent(0, evGate0, 0);
  combine0_kernel<<<(NB*128)/256, 256>>>();
  cudaEventRecord(evC0, 0);

  // s1: gate1 (needs combine0) — overlaps GEMM1 on s0
  cudaStreamWaitEvent(s1, evC0, 0);
  gate1_kernel<<<(NB*32)/256, 256, 0, s1>>>(gw1, gb1);
  cudaEventRecord(evGate1, s1);

  // s0: GEMM1
  bf16_gemm_kernel<1><<<dim3(D2/128, NB/BM, 16), 128, SMEM_GB>>>(w0b, w1b);
  finalize_kernel<<<(16*D2 + 255)/256, 256>>>(1, eg1, ebt1);
  cudaStreamWaitEvent(0, evGate1, 0);
  combine1_kernel<<<(NB*64)/256, 256>>>();

  // towers on the bf16 wmma engine
  bf16_gemm_kernel<2><<<dim3(1, NB/BM, 2), 128, SMEM_GB>>>(w0b, w1b);
  finalize_kernel<<<1, 256>>>(2, tg0, tbt0);
  normrelu_b_kernel<<<(2*NB*32 + 255)/256, 256>>>();
  bf16_gemm_kernel<3><<<dim3(1, NB/BM, 2), 128, SMEM_GB>>>(w0b, w1b);
  finalize_kernel<<<1, 256>>>(3, tg1, tbt1);
  final_kernel<<<(NB*32)/256, 256>>>(tow, tob, out);
}

// round 16
// speedup vs baseline: 1.2070x; 1.2070x over previous
#include <cuda_runtime.h>
#include <cuda_bf16.h>
#include <mma.h>
#include <math.h>
#include <stdint.h>

using namespace nvcuda;

// Problem constants
constexpr int NB   = 16384;
constexpr int NF   = 18;
constexpr int NE   = 64;
constexpr int IN0  = 1152;
constexpr int D1   = 512;
constexpr int D2   = 256;
constexpr int NVOC = 100000;

// ---------------- static device scratch ----------------
__device__ __align__(1024) float d_feat [(size_t)NB*IN0];           // f32 (gate0)
__device__ __align__(1024) __nv_bfloat16 d_featb[(size_t)NB*IN0];   // bf16 (MMA)
__device__ __align__(1024) float d_h0   [(size_t)12*NB*D1];
__device__ __align__(1024) float d_h1   [(size_t)16*NB*D2];
__device__ __align__(1024) float d_fea1 [(size_t)2*NB*D1];          // f32 (gate1)
__device__ __align__(1024) __nv_bfloat16 d_fea1b[(size_t)2*NB*D1];  // bf16 (MMA)
__device__ __align__(1024) __nv_bfloat16 d_fea2b[(size_t)2*NB*D2];  // bf16 (tower MMA)
__device__ __align__(1024) __nv_bfloat16 d_w0b[(size_t)12*IN0*D1];
__device__ __align__(1024) __nv_bfloat16 d_w1b[(size_t)12*D1*D2];
__device__ __align__(1024) __nv_bfloat16 d_tw0b[(size_t)2*D2*128];
__device__ __align__(1024) __nv_bfloat16 d_tw1b[(size_t)2*128*64];
__device__ float d_t1raw[(size_t)2*NB*128];
__device__ __align__(1024) __nv_bfloat16 d_t1b[(size_t)2*NB*128];
__device__ float d_t2raw[(size_t)2*NB*64];
__device__ float d_gate0[(size_t)NB*16];
__device__ float d_gate1[(size_t)NB*16];

__device__ float d_sum0[12*D1], d_sq0[12*D1], d_a0[12*D1], d_c0[12*D1];
__device__ float d_sum1[16*D2], d_sq1[16*D2], d_a1[16*D2], d_c1[16*D2];
__device__ float d_sumT0[2*128], d_sqT0[2*128], d_aT0[2*128], d_cT0[2*128];
__device__ float d_sumT1[2*64],  d_sqT1[2*64],  d_aT1[2*64],  d_cT1[2*64];

__device__ __forceinline__ int expert_of(int z){
  int t = z >> 3, k = z & 7;
  return (k < 4) ? (t*4 + k) : (4 + k);
}

__device__ __forceinline__ void st_bf16x4(__nv_bfloat16* p, float4 v){
  __nv_bfloat162 lo = __floats2bfloat162_rn(v.x, v.y);
  __nv_bfloat162 hi = __floats2bfloat162_rn(v.z, v.w);
  uint2 u; u.x = *(unsigned*)&lo; u.y = *(unsigned*)&hi;
  *(uint2*)p = u;
}

// ---------------- cp.async helpers ----------------
__device__ __forceinline__ uint32_t smem_u32(const void* p){
  uint32_t a;
  asm("{ .reg .u64 t; cvta.to.shared.u64 t, %1; cvt.u32.u64 %0, t; }" : "=r"(a) : "l"(p));
  return a;
}
__device__ __forceinline__ void cp16(uint32_t s, const void* g){
  asm volatile("cp.async.cg.shared.global [%0], [%1], 16;" :: "r"(s), "l"(g) : "memory");
}
#define CP_COMMIT() asm volatile("cp.async.commit_group;" ::: "memory")
#define CP_WAIT(n)  asm volatile("cp.async.wait_group %0;" :: "n"(n) : "memory")

// ---------------- bf16 wmma grouped GEMM, templated on MODE ----------------
constexpr int BM = 128, BKb = 64;
constexpr int S_STG = 3;
constexpr int A_LDb = 72;
constexpr int B_LDb = 136;
constexpr int A_STG_B = BM * A_LDb * 2;
constexpr int B_STG_B = BKb * B_LDb * 2;
constexpr int STG_B   = A_STG_B + B_STG_B;     // 35840
constexpr int SMEM_GB = S_STG * STG_B;         // 107520

typedef wmma::fragment<wmma::matrix_a, 16,16,16, __nv_bfloat16, wmma::row_major> FA;
typedef wmma::fragment<wmma::matrix_b, 16,16,16, __nv_bfloat16, wmma::row_major> FB;
typedef wmma::fragment<wmma::accumulator, 16,16,16, float> FC;

template<int MODE>
__global__ void __launch_bounds__(128,2) bf16_gemm_kernel(const __nv_bfloat16* __restrict__ w0,
                                                          const __nv_bfloat16* __restrict__ w1){
  constexpr int N  = (MODE==0) ? D1 : (MODE==1) ? D2 : (MODE==2) ? 128 : 64;
  constexpr int K  = (MODE==0) ? IN0 : (MODE==1) ? D1 : (MODE==2) ? D2 : 128;
  constexpr int NK = K / BKb;

  extern __shared__ char sm[];
  const uint32_t sb = smem_u32(sm);
  const int tid = threadIdx.x;
  const int wid = tid >> 5;
  const int wm = wid >> 1;
  const int wn = wid & 1;

  const int z = blockIdx.z;
  const __nv_bfloat16* A; const __nv_bfloat16* W;
  __nv_bfloat16* Cb = nullptr; float* Cf = nullptr;
  float* sumP; float* sqP;
  if(MODE == 0){
    A = d_featb;
    W = w0 + (size_t)z*K*N;
    Cf = d_h0 + (size_t)z*NB*N;
    sumP = d_sum0 + z*N; sqP = d_sq0 + z*N;
  } else if(MODE == 1){
    int t = z >> 3, e = expert_of(z);
    A = d_fea1b + (size_t)t*NB*D1;
    W = w1 + (size_t)e*K*N;
    Cf = d_h1 + (size_t)z*NB*N;
    sumP = d_sum1 + z*N; sqP = d_sq1 + z*N;
  } else if(MODE == 2){
    A = d_fea2b + (size_t)z*NB*D2;
    W = d_tw0b + (size_t)z*K*N;
    Cf = d_t1raw + (size_t)z*NB*N;
    sumP = d_sumT0 + z*N; sqP = d_sqT0 + z*N;
  } else {
    A = d_t1b + (size_t)z*NB*128;
    W = d_tw1b + (size_t)z*K*N;
    Cf = d_t2raw + (size_t)z*NB*N;
    sumP = d_sumT1 + z*N; sqP = d_sqT1 + z*N;
  }
  (void)Cb;
  const int m0 = blockIdx.y * BM;
  const int n0 = blockIdx.x * 128;

  // For N<128: zero-fill the never-written B smem columns once.
  if(N < 128){
    for(int i = tid; i < S_STG*B_STG_B/4; i += 128)
      ((uint32_t*)(sm))[ (A_STG_B/4) + (i/(B_STG_B/4))*(STG_B/4) + (i % (B_STG_B/4)) ] = 0;
    __syncthreads();
  }

  const __nv_bfloat16* Abase = A + (size_t)m0 * K;
  const __nv_bfloat16* Bbase = W + n0;

  auto load_stage = [&](int kc, int buf){
    const __nv_bfloat16* gA = Abase + (size_t)kc * BKb;
    const __nv_bfloat16* gB = Bbase + (size_t)kc * BKb * N;
    uint32_t sA = sb + buf * STG_B;
    uint32_t sB = sA + A_STG_B;
    #pragma unroll
    for(int it = 0; it < 8; ++it){
      int idx = it*128 + tid;
      int r = idx >> 3, q = idx & 7;
      cp16(sA + (uint32_t)(r*A_LDb + q*8)*2, gA + (size_t)r*K + q*8);
    }
    #pragma unroll
    for(int it = 0; it < 8; ++it){
      int idx = it*128 + tid;
      int r = idx >> 4, q = idx & 15;
      if(N >= 128 || q*8 < N)
        cp16(sB + (uint32_t)(r*B_LDb + q*8)*2, gB + (size_t)r*N + q*8);
    }
  };

  FC acc[4][4];
  #pragma unroll
  for(int i = 0; i < 4; ++i)
    #pragma unroll
    for(int j = 0; j < 4; ++j) wmma::fill_fragment(acc[i][j], 0.f);

  load_stage(0, 0); CP_COMMIT();
  load_stage(1, 1); CP_COMMIT();

  for(int kc = 0; kc < NK; ++kc){
    CP_WAIT(1);
    __syncthreads();
    int ts = kc + 2;
    if(ts < NK) load_stage(ts, ts % S_STG);
    CP_COMMIT();
    const __nv_bfloat16* As = (const __nv_bfloat16*)(sm + (kc % S_STG) * STG_B);
    const __nv_bfloat16* Bs = (const __nv_bfloat16*)(sm + (kc % S_STG) * STG_B + A_STG_B);
    #pragma unroll
    for(int ks = 0; ks < 4; ++ks){
      FB b[4];
      #pragma unroll
      for(int jn = 0; jn < 4; ++jn)
        wmma::load_matrix_sync(b[jn], Bs + (ks*16)*B_LDb + wn*64 + jn*16, B_LDb);
      #pragma unroll
      for(int im = 0; im < 4; ++im){
        FA a;
        wmma::load_matrix_sync(a, As + (wm*64 + im*16)*A_LDb + ks*16, A_LDb);
        #pragma unroll
        for(int jn = 0; jn < 4; ++jn)
          wmma::mma_sync(acc[im][jn], a, b[jn], acc[im][jn]);
      }
    }
  }
  __syncthreads();

  // ---- epilogue: frags -> smem(f32) -> coalesced f32 gmem + fused BN stats ----
  float* shf = (float*)sm;     // 128 x 132
  #pragma unroll
  for(int im = 0; im < 4; ++im)
    #pragma unroll
    for(int jn = 0; jn < 4; ++jn)
      wmma::store_matrix_sync(shf + (wm*64 + im*16)*132 + wn*64 + jn*16,
                              acc[im][jn], 132, wmma::mem_row_major);
  __syncthreads();

  float* Crow = Cf + (size_t)m0*N + n0;
  #pragma unroll 4
  for(int it = 0; it < 32; ++it){
    int idx = it*128 + tid;
    int row = idx >> 5, q = (idx & 31)*4;
    if(N >= 128 || q < N){
      float4 v = make_float4(shf[row*132+q], shf[row*132+q+1],
                             shf[row*132+q+2], shf[row*132+q+3]);
      *(float4*)(Crow + (size_t)row*N + q) = v;
    }
  }
  {
    int col = tid;
    if(N >= 128 || col < N){
      float s = 0.f, q = 0.f;
      #pragma unroll 8
      for(int r = 0; r < 128; ++r){
        float v = shf[r*132 + col]; s += v; q += v*v;
      }
      atomicAdd(&sumP[n0 + col], s);
      atomicAdd(&sqP[n0 + col], q);
    }
  }
}

// f32 -> bf16 conversion (weights), float4-vectorized
__global__ void conv_bf16_kernel(const float* __restrict__ src, __nv_bfloat16* __restrict__ dst, int n4){
  int i = blockIdx.x*blockDim.x + threadIdx.x;
  if(i >= n4) return;
  float4 v = *(const float4*)(src + (size_t)i*4);
  st_bf16x4(dst + (size_t)i*4, v);
}

// ---------------- small kernels ----------------
__global__ void zero_stats_kernel(){
  int i = blockIdx.x*blockDim.x + threadIdx.x;
  if(i < 12*D1){ d_sum0[i]=0.f; d_sq0[i]=0.f; }
  if(i < 16*D2){ d_sum1[i]=0.f; d_sq1[i]=0.f; }
  if(i < 2*128){ d_sumT0[i]=0.f; d_sqT0[i]=0.f; }
  if(i < 2*64 ){ d_sumT1[i]=0.f; d_sqT1[i]=0.f; }
}

__global__ void gather_kernel(const int* __restrict__ x, const float* __restrict__ emb){
  int idx = blockIdx.x*blockDim.x + threadIdx.x;   // NB*NF*16
  int q = idx & 15;
  int f = (idx >> 4) % NF;
  int b = idx / (16*NF);
  int v = x[b*NF + f];
  float4 val = *(const float4*)(emb + ((size_t)f*NVOC + (size_t)v)*NE + q*4);
  *(float4*)(d_feat + (size_t)b*IN0 + f*NE + q*4) = val;
  st_bf16x4(d_featb + (size_t)b*IN0 + f*NE + q*4, val);
}

__device__ __forceinline__ void warp_reduce16(float* acc){
  #pragma unroll
  for(int off=16; off; off>>=1)
    #pragma unroll
    for(int j=0;j<16;j++) acc[j] += __shfl_xor_sync(0xffffffffu, acc[j], off);
}
__device__ __forceinline__ void softmax8(const float* l, float* o){
  float m = l[0];
  #pragma unroll
  for(int j=1;j<8;j++) m = fmaxf(m, l[j]);
  float s = 0.f, e[8];
  #pragma unroll
  for(int j=0;j<8;j++){ e[j] = expf(l[j]-m); s += e[j]; }
  float inv = 1.f/s;
  #pragma unroll
  for(int j=0;j<8;j++) o[j] = e[j]*inv;
}

__global__ void gate0_kernel(const float* __restrict__ gw, const float* __restrict__ gb){
  int w = (blockIdx.x*blockDim.x + threadIdx.x) >> 5;
  int lane = threadIdx.x & 31;
  if(w >= NB) return;
  const float* frow = d_feat + (size_t)w*IN0;
  float acc[16];
  #pragma unroll
  for(int j=0;j<16;j++) acc[j]=0.f;
  for(int k=lane;k<IN0;k+=32){
    float fv = frow[k];
    const float* g0 = gw + k*8;
    const float* g1 = gw + IN0*8 + k*8;
    #pragma unroll
    for(int j=0;j<8;j++){ acc[j] += fv*g0[j]; acc[8+j] += fv*g1[j]; }
  }
  warp_reduce16(acc);
  if(lane==0){
    float l[8], o[8];
    #pragma unroll
    for(int t=0;t<2;t++){
      #pragma unroll
      for(int j=0;j<8;j++) l[j] = acc[t*8+j] + gb[t*8+j];
      softmax8(l,o);
      #pragma unroll
      for(int j=0;j<8;j++) d_gate0[(size_t)w*16 + t*8 + j] = o[j];
    }
  }
}

__global__ void gate1_kernel(const float* __restrict__ gw, const float* __restrict__ gb){
  int w = (blockIdx.x*blockDim.x + threadIdx.x) >> 5;
  int lane = threadIdx.x & 31;
  if(w >= NB) return;
  const float* f0 = d_fea1 + (size_t)w*D1;
  const float* f1 = d_fea1 + (size_t)NB*D1 + (size_t)w*D1;
  float acc[16];
  #pragma unroll
  for(int j=0;j<16;j++) acc[j]=0.f;
  for(int k=lane;k<D1;k+=32){
    float v0 = f0[k], v1 = f1[k];
    const float* g0 = gw + k*8;
    const float* g1 = gw + D1*8 + k*8;
    #pragma unroll
    for(int j=0;j<8;j++){ acc[j] += v0*g0[j]; acc[8+j] += v1*g1[j]; }
  }
  warp_reduce16(acc);
  if(lane==0){
    float l[8], o[8];
    #pragma unroll
    for(int t=0;t<2;t++){
      #pragma unroll
      for(int j=0;j<8;j++) l[j] = acc[t*8+j] + gb[t*8+j];
      softmax8(l,o);
      #pragma unroll
      for(int j=0;j<8;j++) d_gate1[(size_t)w*16 + t*8 + j] = o[j];
    }
  }
}

__global__ void finalize_kernel(int mode, const float* __restrict__ g, const float* __restrict__ bt){
  int i = blockIdx.x*blockDim.x + threadIdx.x;
  const float* sum; const float* sq; float* a; float* c; int N, NZ;
  if(mode==0){ sum=d_sum0; sq=d_sq0; a=d_a0; c=d_c0; N=D1; NZ=12; }
  else if(mode==1){ sum=d_sum1; sq=d_sq1; a=d_a1; c=d_c1; N=D2; NZ=16; }
  else if(mode==2){ sum=d_sumT0; sq=d_sqT0; a=d_aT0; c=d_cT0; N=128; NZ=2; }
  else { sum=d_sumT1; sq=d_sqT1; a=d_aT1; c=d_cT1; N=64; NZ=2; }
  if(i >= NZ*N) return;
  int z = i / N, o = i - z*N;
  int gz = (mode==1) ? expert_of(z) : z;
  float mu  = sum[i] * (1.f/NB);
  float var = sq[i] * (1.f/NB) - mu*mu;
  float aa  = g[gz*N+o] * rsqrtf(var + 1e-5f);
  a[i] = aa;
  c[i] = bt[gz*N+o] - mu*aa;
}

// combine0: BN+relu per expert, gate-weighted sums -> f32 fea1 + bf16 fea1b
__global__ void combine0_kernel(){
  int idx = blockIdx.x*blockDim.x + threadIdx.x;   // NB*128
  int o4 = (idx & 127)*4;
  size_t b = (size_t)(idx >> 7);
  const float* g = d_gate0 + b*16;
  float4 acc0 = make_float4(0,0,0,0), acc1 = make_float4(0,0,0,0);
  #pragma unroll
  for(int e=0;e<12;e++){
    float4 h = *(const float4*)(d_h0 + ((size_t)e*NB + b)*D1 + o4);
    float4 a = *(const float4*)(d_a0 + e*D1 + o4);
    float4 c = *(const float4*)(d_c0 + e*D1 + o4);
    float4 y;
    y.x = fmaxf(h.x*a.x + c.x, 0.f);
    y.y = fmaxf(h.y*a.y + c.y, 0.f);
    y.z = fmaxf(h.z*a.z + c.z, 0.f);
    y.w = fmaxf(h.w*a.w + c.w, 0.f);
    float g0 = (e < 4) ? g[e] : ((e >= 8) ? g[e-4] : 0.f);
    float g1 = (e >= 4) ? g[8 + e - 4] : 0.f;
    acc0.x += g0*y.x; acc0.y += g0*y.y; acc0.z += g0*y.z; acc0.w += g0*y.w;
    acc1.x += g1*y.x; acc1.y += g1*y.y; acc1.z += g1*y.z; acc1.w += g1*y.w;
  }
  *(float4*)(d_fea1 + b*D1 + o4) = acc0;
  *(float4*)(d_fea1 + (size_t)NB*D1 + b*D1 + o4) = acc1;
  st_bf16x4(d_fea1b + b*D1 + o4, acc0);
  st_bf16x4(d_fea1b + (size_t)NB*D1 + b*D1 + o4, acc1);
}

// combine1: -> bf16 fea2b (only consumer is the tower wmma GEMM)
__global__ void combine1_kernel(){
  int idx = blockIdx.x*blockDim.x + threadIdx.x;   // NB*64
  int o4 = (idx & 63)*4;
  size_t b = (size_t)(idx >> 6);
  const float* g = d_gate1 + b*16;
  float4 acc0 = make_float4(0,0,0,0), acc1 = make_float4(0,0,0,0);
  #pragma unroll
  for(int s=0;s<16;s++){
    float4 h = *(const float4*)(d_h1 + ((size_t)s*NB + b)*D2 + o4);
    float4 a = *(const float4*)(d_a1 + s*D2 + o4);
    float4 c = *(const float4*)(d_c1 + s*D2 + o4);
    float4 y;
    y.x = fmaxf(h.x*a.x + c.x, 0.f);
    y.y = fmaxf(h.y*a.y + c.y, 0.f);
    y.z = fmaxf(h.z*a.z + c.z, 0.f);
    y.w = fmaxf(h.w*a.w + c.w, 0.f);
    float gv = g[s];
    if(s < 8){ acc0.x += gv*y.x; acc0.y += gv*y.y; acc0.z += gv*y.z; acc0.w += gv*y.w; }
    else     { acc1.x += gv*y.x; acc1.y += gv*y.y; acc1.z += gv*y.z; acc1.w += gv*y.w; }
  }
  st_bf16x4(d_fea2b + b*D2 + o4, acc0);
  st_bf16x4(d_fea2b + (size_t)NB*D2 + b*D2 + o4, acc1);
}

// tower BN1 + relu -> bf16 t1
__global__ void normrelu_b_kernel(){
  int i = blockIdx.x*blockDim.x + threadIdx.x;   // 2*NB*32
  if(i >= 2*NB*32) return;
  int o4 = (i & 31)*4;
  int row = i >> 5;
  int t = row / NB;
  float4 h = *(const float4*)(d_t1raw + (size_t)row*128 + o4);
  const float* a = d_aT0 + t*128 + o4;
  const float* c = d_cT0 + t*128 + o4;
  float4 y;
  y.x = fmaxf(h.x*a[0] + c[0], 0.f);
  y.y = fmaxf(h.y*a[1] + c[1], 0.f);
  y.z = fmaxf(h.z*a[2] + c[2], 0.f);
  y.w = fmaxf(h.w*a[3] + c[3], 0.f);
  st_bf16x4(d_t1b + (size_t)row*128 + o4, y);
}

// final: tower BN2 + relu inline on t2raw, then dot + sigmoid
__global__ void final_kernel(const float* __restrict__ tow, const float* __restrict__ tob,
                             float* __restrict__ out){
  int w = (blockIdx.x*blockDim.x + threadIdx.x) >> 5;
  int lane = threadIdx.x & 31;
  if(w >= NB) return;
  size_t b = (size_t)w;
  float v0a = fmaxf(d_t2raw[b*64 + lane]*d_aT1[lane] + d_cT1[lane], 0.f);
  float v0b = fmaxf(d_t2raw[b*64 + lane + 32]*d_aT1[lane + 32] + d_cT1[lane + 32], 0.f);
  float v1a = fmaxf(d_t2raw[(size_t)NB*64 + b*64 + lane]*d_aT1[64 + lane] + d_cT1[64 + lane], 0.f);
  float v1b = fmaxf(d_t2raw[(size_t)NB*64 + b*64 + lane + 32]*d_aT1[64 + lane + 32] + d_cT1[64 + lane + 32], 0.f);
  float s0 = v0a*tow[lane] + v0b*tow[lane + 32];
  float s1 = v1a*tow[64 + lane] + v1b*tow[64 + lane + 32];
  #pragma unroll
  for(int off=16; off; off>>=1){
    s0 += __shfl_xor_sync(0xffffffffu, s0, off);
    s1 += __shfl_xor_sync(0xffffffffu, s1, off);
  }
  if(lane==0){
    out[b]      = 1.f/(1.f + expf(-(s0 + tob[0])));
    out[NB + b] = 1.f/(1.f + expf(-(s1 + tob[1])));
  }
}

// ---------------- host launcher ----------------
extern "C" void kernel_launch(void* const* d_in, const int* in_sizes, int n_in,
                              void* d_out, int out_size){
  const int*   x    = (const int*)  d_in[0];
  const float* emb  = (const float*)d_in[1];
  const float* ew0  = (const float*)d_in[2];
  const float* eg0  = (const float*)d_in[4];
  const float* ebt0 = (const float*)d_in[5];
  const float* gw0  = (const float*)d_in[6];
  const float* gb0  = (const float*)d_in[7];
  const float* ew1  = (const float*)d_in[10];
  const float* eg1  = (const float*)d_in[12];
  const float* ebt1 = (const float*)d_in[13];
  const float* gw1  = (const float*)d_in[14];
  const float* gb1  = (const float*)d_in[15];
  const float* tw0  = (const float*)d_in[18];
  const float* tg0  = (const float*)d_in[20];
  const float* tbt0 = (const float*)d_in[21];
  const float* tw1  = (const float*)d_in[22];
  const float* tg1  = (const float*)d_in[24];
  const float* tbt1 = (const float*)d_in[25];
  const float* tow  = (const float*)d_in[26];
  const float* tob  = (const float*)d_in[27];
  float* out = (float*)d_out;

  static bool init_done = false;
  static cudaStream_t s1 = nullptr;
  static cudaEvent_t evRoot, evConv, evG, evGate0, evC0, evGate1;
  if(!init_done){
    cudaFuncSetAttribute(bf16_gemm_kernel<0>, cudaFuncAttributeMaxDynamicSharedMemorySize, SMEM_GB);
    cudaFuncSetAttribute(bf16_gemm_kernel<1>, cudaFuncAttributeMaxDynamicSharedMemorySize, SMEM_GB);
    cudaFuncSetAttribute(bf16_gemm_kernel<2>, cudaFuncAttributeMaxDynamicSharedMemorySize, SMEM_GB);
    cudaFuncSetAttribute(bf16_gemm_kernel<3>, cudaFuncAttributeMaxDynamicSharedMemorySize, SMEM_GB);
    cudaStreamCreateWithFlags(&s1, cudaStreamNonBlocking);
    cudaEventCreateWithFlags(&evRoot,  cudaEventDisableTiming);
    cudaEventCreateWithFlags(&evConv,  cudaEventDisableTiming);
    cudaEventCreateWithFlags(&evG,     cudaEventDisableTiming);
    cudaEventCreateWithFlags(&evGate0, cudaEventDisableTiming);
    cudaEventCreateWithFlags(&evC0,    cudaEventDisableTiming);
    cudaEventCreateWithFlags(&evGate1, cudaEventDisableTiming);
    init_done = true;
  }

  __nv_bfloat16* w0b;  cudaGetSymbolAddress((void**)&w0b,  d_w0b);
  __nv_bfloat16* w1b;  cudaGetSymbolAddress((void**)&w1b,  d_w1b);
  __nv_bfloat16* tw0b; cudaGetSymbolAddress((void**)&tw0b, d_tw0b);
  __nv_bfloat16* tw1b; cudaGetSymbolAddress((void**)&tw1b, d_tw1b);

  // fork side stream from capture stream
  cudaEventRecord(evRoot, 0);
  cudaStreamWaitEvent(s1, evRoot, 0);

  // s1: zero stats + all weight conversions (independent of gather)
  zero_stats_kernel<<<(12*D1 + 255)/256, 256, 0, s1>>>();
  conv_bf16_kernel<<<(12*IN0*D1/4 + 255)/256, 256, 0, s1>>>(ew0, w0b, 12*IN0*D1/4);
  conv_bf16_kernel<<<(12*D1*D2/4 + 255)/256, 256, 0, s1>>>(ew1, w1b, 12*D1*D2/4);
  conv_bf16_kernel<<<(2*D2*128/4 + 255)/256, 256, 0, s1>>>(tw0, tw0b, 2*D2*128/4);
  conv_bf16_kernel<<<(2*128*64/4 + 255)/256, 256, 0, s1>>>(tw1, tw1b, 2*128*64/4);
  cudaEventRecord(evConv, s1);

  // s0: gather
  gather_kernel<<<(NB*NF*16)/256, 256>>>(x, emb);
  cudaEventRecord(evG, 0);

  // s1: gate0 (needs gather) — overlaps GEMM0 on s0
  cudaStreamWaitEvent(s1, evG, 0);
  gate0_kernel<<<(NB*32)/256, 256, 0, s1>>>(gw0, gb0);
  cudaEventRecord(evGate0, s1);

  // s0: GEMM0 (needs conv + zero)
  cudaStreamWaitEvent(0, evConv, 0);
  bf16_gemm_kernel<0><<<dim3(D1/128, NB/BM, 12), 128, SMEM_GB>>>(w0b, w1b);
  finalize_kernel<<<(12*D1 + 255)/256, 256>>>(0, eg0, ebt0);
  cudaStreamWaitEvent(0, evGate0, 0);
  combine0_kernel<<<(NB*128)/256, 256>>>();
  cudaEventRecord(evC0, 0);

  // s1: gate1 (needs combine0) — overlaps GEMM1 on s0
  cudaStreamWaitEvent(s1, evC0, 0);
  gate1_kernel<<<(NB*32)/256, 256, 0, s1>>>(gw1, gb1);
  cudaEventRecord(evGate1, s1);

  // s0: GEMM1
  bf16_gemm_kernel<1><<<dim3(D2/128, NB/BM, 16), 128, SMEM_GB>>>(w0b, w1b);
  finalize_kernel<<<(16*D2 + 255)/256, 256>>>(1, eg1, ebt1);
  cudaStreamWaitEvent(0, evGate1, 0);
  combine1_kernel<<<(NB*64)/256, 256>>>();

  // towers on the bf16 wmma engine (templated, clean codegen per mode)
  bf16_gemm_kernel<2><<<dim3(1, NB/BM, 2), 128, SMEM_GB>>>(w0b, w1b);
  finalize_kernel<<<1, 256>>>(2, tg0, tbt0);
  normrelu_b_kernel<<<(2*NB*32 + 255)/256, 256>>>();
  bf16_gemm_kernel<3><<<dim3(1, NB/BM, 2), 128, SMEM_GB>>>(w0b, w1b);
  finalize_kernel<<<1, 256>>>(3, tg1, tbt1);
  final_kernel<<<(NB*32)/256, 256>>>(tow, tob, out);
}

// round 17
// speedup vs baseline: 1.2130x; 1.0050x over previous
#include <cuda_runtime.h>
#include <cuda_bf16.h>
#include <mma.h>
#include <math.h>
#include <stdint.h>

using namespace nvcuda;

// Problem constants
constexpr int NB   = 16384;
constexpr int NF   = 18;
constexpr int NE   = 64;
constexpr int IN0  = 1152;
constexpr int D1   = 512;
constexpr int D2   = 256;
constexpr int NVOC = 100000;

// ---------------- static device scratch ----------------
__device__ __align__(1024) float d_feat [(size_t)NB*IN0];           // f32 (gate0)
__device__ __align__(1024) __nv_bfloat16 d_featb[(size_t)NB*IN0];   // bf16 (MMA)
__device__ __align__(1024) float d_h0   [(size_t)12*NB*D1];
__device__ __align__(1024) float d_h1   [(size_t)16*NB*D2];
__device__ __align__(1024) float d_fea1 [(size_t)2*NB*D1];          // f32 (gate1)
__device__ __align__(1024) __nv_bfloat16 d_fea1b[(size_t)2*NB*D1];  // bf16 (MMA)
__device__ __align__(1024) __nv_bfloat16 d_fea2b[(size_t)2*NB*D2];  // bf16 (tower MMA)
__device__ __align__(1024) __nv_bfloat16 d_w0b[(size_t)12*IN0*D1];
__device__ __align__(1024) __nv_bfloat16 d_w1b[(size_t)12*D1*D2];
__device__ __align__(1024) __nv_bfloat16 d_tw0b[(size_t)2*D2*128];
__device__ __align__(1024) __nv_bfloat16 d_tw1b[(size_t)2*128*64];
__device__ float d_t1raw[(size_t)2*NB*128];
__device__ __align__(1024) __nv_bfloat16 d_t1b[(size_t)2*NB*128];
__device__ float d_t2raw[(size_t)2*NB*64];
__device__ float d_gate0[(size_t)NB*16];
__device__ float d_gate1[(size_t)NB*16];

__device__ float d_sum0[12*D1], d_sq0[12*D1], d_a0[12*D1], d_c0[12*D1];
__device__ float d_sum1[16*D2], d_sq1[16*D2], d_a1[16*D2], d_c1[16*D2];
__device__ float d_sumT0[2*128], d_sqT0[2*128];
__device__ float d_sumT1[2*64],  d_sqT1[2*64];

__device__ __forceinline__ int expert_of(int z){
  int t = z >> 3, k = z & 7;
  return (k < 4) ? (t*4 + k) : (4 + k);
}

__device__ __forceinline__ void st_bf16x4(__nv_bfloat16* p, float4 v){
  __nv_bfloat162 lo = __floats2bfloat162_rn(v.x, v.y);
  __nv_bfloat162 hi = __floats2bfloat162_rn(v.z, v.w);
  uint2 u; u.x = *(unsigned*)&lo; u.y = *(unsigned*)&hi;
  *(uint2*)p = u;
}

// ---------------- cp.async helpers ----------------
__device__ __forceinline__ uint32_t smem_u32(const void* p){
  uint32_t a;
  asm("{ .reg .u64 t; cvta.to.shared.u64 t, %1; cvt.u32.u64 %0, t; }" : "=r"(a) : "l"(p));
  return a;
}
__device__ __forceinline__ void cp16(uint32_t s, const void* g){
  asm volatile("cp.async.cg.shared.global [%0], [%1], 16;" :: "r"(s), "l"(g) : "memory");
}
#define CP_COMMIT() asm volatile("cp.async.commit_group;" ::: "memory")
#define CP_WAIT(n)  asm volatile("cp.async.wait_group %0;" :: "n"(n) : "memory")

// ---------------- bf16 wmma grouped GEMM, templated on MODE ----------------
constexpr int BM = 128, BKb = 64;
constexpr int S_STG = 3;
constexpr int A_LDb = 72;
constexpr int B_LDb = 136;
constexpr int A_STG_B = BM * A_LDb * 2;
constexpr int B_STG_B = BKb * B_LDb * 2;
constexpr int STG_B   = A_STG_B + B_STG_B;     // 35840
constexpr int SMEM_GB = S_STG * STG_B;         // 107520

typedef wmma::fragment<wmma::matrix_a, 16,16,16, __nv_bfloat16, wmma::row_major> FA;
typedef wmma::fragment<wmma::matrix_b, 16,16,16, __nv_bfloat16, wmma::row_major> FB;
typedef wmma::fragment<wmma::accumulator, 16,16,16, float> FC;

template<int MODE>
__global__ void __launch_bounds__(128,2) bf16_gemm_kernel(const __nv_bfloat16* __restrict__ w0,
                                                          const __nv_bfloat16* __restrict__ w1){
  constexpr int N  = (MODE==0) ? D1 : (MODE==1) ? D2 : (MODE==2) ? 128 : 64;
  constexpr int K  = (MODE==0) ? IN0 : (MODE==1) ? D1 : (MODE==2) ? D2 : 128;
  constexpr int NK = K / BKb;

  extern __shared__ char sm[];
  const uint32_t sb = smem_u32(sm);
  const int tid = threadIdx.x;
  const int wid = tid >> 5;
  const int wm = wid >> 1;
  const int wn = wid & 1;

  const int z = blockIdx.z;
  const __nv_bfloat16* A; const __nv_bfloat16* W; float* Cf;
  float* sumP; float* sqP;
  if(MODE == 0){
    A = d_featb;
    W = w0 + (size_t)z*K*N;
    Cf = d_h0 + (size_t)z*NB*N;
    sumP = d_sum0 + z*N; sqP = d_sq0 + z*N;
  } else if(MODE == 1){
    int t = z >> 3, e = expert_of(z);
    A = d_fea1b + (size_t)t*NB*D1;
    W = w1 + (size_t)e*K*N;
    Cf = d_h1 + (size_t)z*NB*N;
    sumP = d_sum1 + z*N; sqP = d_sq1 + z*N;
  } else if(MODE == 2){
    A = d_fea2b + (size_t)z*NB*D2;
    W = d_tw0b + (size_t)z*K*N;
    Cf = d_t1raw + (size_t)z*NB*N;
    sumP = d_sumT0 + z*N; sqP = d_sqT0 + z*N;
  } else {
    A = d_t1b + (size_t)z*NB*128;
    W = d_tw1b + (size_t)z*K*N;
    Cf = d_t2raw + (size_t)z*NB*N;
    sumP = d_sumT1 + z*N; sqP = d_sqT1 + z*N;
  }
  const int m0 = blockIdx.y * BM;
  const int n0 = blockIdx.x * 128;

  // For N<128: zero-fill the never-written B smem columns once.
  if(N < 128){
    for(int i = tid; i < S_STG*B_STG_B/4; i += 128)
      ((uint32_t*)(sm))[ (A_STG_B/4) + (i/(B_STG_B/4))*(STG_B/4) + (i % (B_STG_B/4)) ] = 0;
    __syncthreads();
  }

  const __nv_bfloat16* Abase = A + (size_t)m0 * K;
  const __nv_bfloat16* Bbase = W + n0;

  auto load_stage = [&](int kc, int buf){
    const __nv_bfloat16* gA = Abase + (size_t)kc * BKb;
    const __nv_bfloat16* gB = Bbase + (size_t)kc * BKb * N;
    uint32_t sA = sb + buf * STG_B;
    uint32_t sB = sA + A_STG_B;
    #pragma unroll
    for(int it = 0; it < 8; ++it){
      int idx = it*128 + tid;
      int r = idx >> 3, q = idx & 7;
      cp16(sA + (uint32_t)(r*A_LDb + q*8)*2, gA + (size_t)r*K + q*8);
    }
    #pragma unroll
    for(int it = 0; it < 8; ++it){
      int idx = it*128 + tid;
      int r = idx >> 4, q = idx & 15;
      if(N >= 128 || q*8 < N)
        cp16(sB + (uint32_t)(r*B_LDb + q*8)*2, gB + (size_t)r*N + q*8);
    }
  };

  FC acc[4][4];
  #pragma unroll
  for(int i = 0; i < 4; ++i)
    #pragma unroll
    for(int j = 0; j < 4; ++j) wmma::fill_fragment(acc[i][j], 0.f);

  load_stage(0, 0); CP_COMMIT();
  load_stage(1, 1); CP_COMMIT();

  for(int kc = 0; kc < NK; ++kc){
    CP_WAIT(1);
    __syncthreads();
    int ts = kc + 2;
    if(ts < NK) load_stage(ts, ts % S_STG);
    CP_COMMIT();
    const __nv_bfloat16* As = (const __nv_bfloat16*)(sm + (kc % S_STG) * STG_B);
    const __nv_bfloat16* Bs = (const __nv_bfloat16*)(sm + (kc % S_STG) * STG_B + A_STG_B);
    #pragma unroll
    for(int ks = 0; ks < 4; ++ks){
      FB b[4];
      #pragma unroll
      for(int jn = 0; jn < 4; ++jn)
        wmma::load_matrix_sync(b[jn], Bs + (ks*16)*B_LDb + wn*64 + jn*16, B_LDb);
      #pragma unroll
      for(int im = 0; im < 4; ++im){
        FA a;
        wmma::load_matrix_sync(a, As + (wm*64 + im*16)*A_LDb + ks*16, A_LDb);
        #pragma unroll
        for(int jn = 0; jn < 4; ++jn)
          wmma::mma_sync(acc[im][jn], a, b[jn], acc[im][jn]);
      }
    }
  }
  __syncthreads();

  // ---- epilogue: frags -> smem(f32) -> coalesced f32 gmem + fused BN stats ----
  float* shf = (float*)sm;     // 128 x 132
  #pragma unroll
  for(int im = 0; im < 4; ++im)
    #pragma unroll
    for(int jn = 0; jn < 4; ++jn)
      wmma::store_matrix_sync(shf + (wm*64 + im*16)*132 + wn*64 + jn*16,
                              acc[im][jn], 132, wmma::mem_row_major);
  __syncthreads();

  float* Crow = Cf + (size_t)m0*N + n0;
  #pragma unroll 4
  for(int it = 0; it < 32; ++it){
    int idx = it*128 + tid;
    int row = idx >> 5, q = (idx & 31)*4;
    if(N >= 128 || q < N){
      float4 v = make_float4(shf[row*132+q], shf[row*132+q+1],
                             shf[row*132+q+2], shf[row*132+q+3]);
      *(float4*)(Crow + (size_t)row*N + q) = v;
    }
  }
  {
    int col = tid;
    if(N >= 128 || col < N){
      float s = 0.f, q = 0.f;
      #pragma unroll 8
      for(int r = 0; r < 128; ++r){
        float v = shf[r*132 + col]; s += v; q += v*v;
      }
      atomicAdd(&sumP[n0 + col], s);
      atomicAdd(&sqP[n0 + col], q);
    }
  }
}

// f32 -> bf16 conversion (weights), float4-vectorized
__global__ void conv_bf16_kernel(const float* __restrict__ src, __nv_bfloat16* __restrict__ dst, int n4){
  int i = blockIdx.x*blockDim.x + threadIdx.x;
  if(i >= n4) return;
  float4 v = *(const float4*)(src + (size_t)i*4);
  st_bf16x4(dst + (size_t)i*4, v);
}

// ---------------- small kernels ----------------
__global__ void zero_stats_kernel(){
  int i = blockIdx.x*blockDim.x + threadIdx.x;
  if(i < 12*D1){ d_sum0[i]=0.f; d_sq0[i]=0.f; }
  if(i < 16*D2){ d_sum1[i]=0.f; d_sq1[i]=0.f; }
  if(i < 2*128){ d_sumT0[i]=0.f; d_sqT0[i]=0.f; }
  if(i < 2*64 ){ d_sumT1[i]=0.f; d_sqT1[i]=0.f; }
}

__global__ void gather_kernel(const int* __restrict__ x, const float* __restrict__ emb){
  int idx = blockIdx.x*blockDim.x + threadIdx.x;   // NB*NF*16
  int q = idx & 15;
  int f = (idx >> 4) % NF;
  int b = idx / (16*NF);
  int v = x[b*NF + f];
  float4 val = *(const float4*)(emb + ((size_t)f*NVOC + (size_t)v)*NE + q*4);
  *(float4*)(d_feat + (size_t)b*IN0 + f*NE + q*4) = val;
  st_bf16x4(d_featb + (size_t)b*IN0 + f*NE + q*4, val);
}

__device__ __forceinline__ void warp_reduce16(float* acc){
  #pragma unroll
  for(int off=16; off; off>>=1)
    #pragma unroll
    for(int j=0;j<16;j++) acc[j] += __shfl_xor_sync(0xffffffffu, acc[j], off);
}
__device__ __forceinline__ void softmax8(const float* l, float* o){
  float m = l[0];
  #pragma unroll
  for(int j=1;j<8;j++) m = fmaxf(m, l[j]);
  float s = 0.f, e[8];
  #pragma unroll
  for(int j=0;j<8;j++){ e[j] = expf(l[j]-m); s += e[j]; }
  float inv = 1.f/s;
  #pragma unroll
  for(int j=0;j<8;j++) o[j] = e[j]*inv;
}

__global__ void gate0_kernel(const float* __restrict__ gw, const float* __restrict__ gb){
  int w = (blockIdx.x*blockDim.x + threadIdx.x) >> 5;
  int lane = threadIdx.x & 31;
  if(w >= NB) return;
  const float* frow = d_feat + (size_t)w*IN0;
  float acc[16];
  #pragma unroll
  for(int j=0;j<16;j++) acc[j]=0.f;
  for(int k=lane;k<IN0;k+=32){
    float fv = frow[k];
    const float* g0 = gw + k*8;
    const float* g1 = gw + IN0*8 + k*8;
    #pragma unroll
    for(int j=0;j<8;j++){ acc[j] += fv*g0[j]; acc[8+j] += fv*g1[j]; }
  }
  warp_reduce16(acc);
  if(lane==0){
    float l[8], o[8];
    #pragma unroll
    for(int t=0;t<2;t++){
      #pragma unroll
      for(int j=0;j<8;j++) l[j] = acc[t*8+j] + gb[t*8+j];
      softmax8(l,o);
      #pragma unroll
      for(int j=0;j<8;j++) d_gate0[(size_t)w*16 + t*8 + j] = o[j];
    }
  }
}

__global__ void gate1_kernel(const float* __restrict__ gw, const float* __restrict__ gb){
  int w = (blockIdx.x*blockDim.x + threadIdx.x) >> 5;
  int lane = threadIdx.x & 31;
  if(w >= NB) return;
  const float* f0 = d_fea1 + (size_t)w*D1;
  const float* f1 = d_fea1 + (size_t)NB*D1 + (size_t)w*D1;
  float acc[16];
  #pragma unroll
  for(int j=0;j<16;j++) acc[j]=0.f;
  for(int k=lane;k<D1;k+=32){
    float v0 = f0[k], v1 = f1[k];
    const float* g0 = gw + k*8;
    const float* g1 = gw + D1*8 + k*8;
    #pragma unroll
    for(int j=0;j<8;j++){ acc[j] += v0*g0[j]; acc[8+j] += v1*g1[j]; }
  }
  warp_reduce16(acc);
  if(lane==0){
    float l[8], o[8];
    #pragma unroll
    for(int t=0;t<2;t++){
      #pragma unroll
      for(int j=0;j<8;j++) l[j] = acc[t*8+j] + gb[t*8+j];
      softmax8(l,o);
      #pragma unroll
      for(int j=0;j<8;j++) d_gate1[(size_t)w*16 + t*8 + j] = o[j];
    }
  }
}

// finalize for MoE layers (modes 0/1 only — tower finalize is fused downstream)
__global__ void finalize_kernel(int mode, const float* __restrict__ g, const float* __restrict__ bt){
  int i = blockIdx.x*blockDim.x + threadIdx.x;
  const float* sum; const float* sq; float* a; float* c; int N, NZ;
  if(mode==0){ sum=d_sum0; sq=d_sq0; a=d_a0; c=d_c0; N=D1; NZ=12; }
  else        { sum=d_sum1; sq=d_sq1; a=d_a1; c=d_c1; N=D2; NZ=16; }
  if(i >= NZ*N) return;
  int z = i / N, o = i - z*N;
  int gz = (mode==1) ? expert_of(z) : z;
  float mu  = sum[i] * (1.f/NB);
  float var = sq[i] * (1.f/NB) - mu*mu;
  float aa  = g[gz*N+o] * rsqrtf(var + 1e-5f);
  a[i] = aa;
  c[i] = bt[gz*N+o] - mu*aa;
}

// combine0: BN+relu per expert, gate-weighted sums -> f32 fea1 + bf16 fea1b
__global__ void combine0_kernel(){
  int idx = blockIdx.x*blockDim.x + threadIdx.x;   // NB*128
  int o4 = (idx & 127)*4;
  size_t b = (size_t)(idx >> 7);
  const float* g = d_gate0 + b*16;
  float4 acc0 = make_float4(0,0,0,0), acc1 = make_float4(0,0,0,0);
  #pragma unroll
  for(int e=0;e<12;e++){
    float4 h = *(const float4*)(d_h0 + ((size_t)e*NB + b)*D1 + o4);
    float4 a = *(const float4*)(d_a0 + e*D1 + o4);
    float4 c = *(const float4*)(d_c0 + e*D1 + o4);
    float4 y;
    y.x = fmaxf(h.x*a.x + c.x, 0.f);
    y.y = fmaxf(h.y*a.y + c.y, 0.f);
    y.z = fmaxf(h.z*a.z + c.z, 0.f);
    y.w = fmaxf(h.w*a.w + c.w, 0.f);
    float g0 = (e < 4) ? g[e] : ((e >= 8) ? g[e-4] : 0.f);
    float g1 = (e >= 4) ? g[8 + e - 4] : 0.f;
    acc0.x += g0*y.x; acc0.y += g0*y.y; acc0.z += g0*y.z; acc0.w += g0*y.w;
    acc1.x += g1*y.x; acc1.y += g1*y.y; acc1.z += g1*y.z; acc1.w += g1*y.w;
  }
  *(float4*)(d_fea1 + b*D1 + o4) = acc0;
  *(float4*)(d_fea1 + (size_t)NB*D1 + b*D1 + o4) = acc1;
  st_bf16x4(d_fea1b + b*D1 + o4, acc0);
  st_bf16x4(d_fea1b + (size_t)NB*D1 + b*D1 + o4, acc1);
}

// combine1: -> bf16 fea2b (only consumer is the tower wmma GEMM)
__global__ void combine1_kernel(){
  int idx = blockIdx.x*blockDim.x + threadIdx.x;   // NB*64
  int o4 = (idx & 63)*4;
  size_t b = (size_t)(idx >> 6);
  const float* g = d_gate1 + b*16;
  float4 acc0 = make_float4(0,0,0,0), acc1 = make_float4(0,0,0,0);
  #pragma unroll
  for(int s=0;s<16;s++){
    float4 h = *(const float4*)(d_h1 + ((size_t)s*NB + b)*D2 + o4);
    float4 a = *(const float4*)(d_a1 + s*D2 + o4);
    float4 c = *(const float4*)(d_c1 + s*D2 + o4);
    float4 y;
    y.x = fmaxf(h.x*a.x + c.x, 0.f);
    y.y = fmaxf(h.y*a.y + c.y, 0.f);
    y.z = fmaxf(h.z*a.z + c.z, 0.f);
    y.w = fmaxf(h.w*a.w + c.w, 0.f);
    float gv = g[s];
    if(s < 8){ acc0.x += gv*y.x; acc0.y += gv*y.y; acc0.z += gv*y.z; acc0.w += gv*y.w; }
    else     { acc1.x += gv*y.x; acc1.y += gv*y.y; acc1.z += gv*y.z; acc1.w += gv*y.w; }
  }
  st_bf16x4(d_fea2b + b*D2 + o4, acc0);
  st_bf16x4(d_fea2b + (size_t)NB*D2 + b*D2 + o4, acc1);
}

// tower BN1 + relu -> bf16 t1 (fuses finalize(2): per-block affine from raw stats)
__global__ void normrelu_b_kernel(const float* __restrict__ tg0, const float* __restrict__ tbt0){
  __shared__ float sA[128], sC[128];
  // all 8 rows of this block share one task t (2048-block boundary = NB rows)
  int t_blk = (int)((blockIdx.x * (unsigned)blockDim.x) >> 5) / NB;
  if(threadIdx.x < 128){
    int i = t_blk*128 + threadIdx.x;
    float mu  = d_sumT0[i] * (1.f/NB);
    float var = d_sqT0[i] * (1.f/NB) - mu*mu;
    float aa  = tg0[i] * rsqrtf(var + 1e-5f);
    sA[threadIdx.x] = aa;
    sC[threadIdx.x] = tbt0[i] - mu*aa;
  }
  __syncthreads();
  int i = blockIdx.x*blockDim.x + threadIdx.x;   // 2*NB*32
  if(i >= 2*NB*32) return;
  int o4 = (i & 31)*4;
  int row = i >> 5;
  float4 h = *(const float4*)(d_t1raw + (size_t)row*128 + o4);
  float4 y;
  y.x = fmaxf(h.x*sA[o4+0] + sC[o4+0], 0.f);
  y.y = fmaxf(h.y*sA[o4+1] + sC[o4+1], 0.f);
  y.z = fmaxf(h.z*sA[o4+2] + sC[o4+2], 0.f);
  y.w = fmaxf(h.w*sA[o4+3] + sC[o4+3], 0.f);
  st_bf16x4(d_t1b + (size_t)row*128 + o4, y);
}

// final: fuses finalize(3) (per-block affine) + BN2 + relu + dot + sigmoid
__global__ void final_kernel(const float* __restrict__ tg1, const float* __restrict__ tbt1,
                             const float* __restrict__ tow, const float* __restrict__ tob,
                             float* __restrict__ out){
  __shared__ float sA[128], sC[128];   // both tasks' 64-ch affine params
  if(threadIdx.x < 128){
    int i = threadIdx.x;               // i = t*64 + o
    float mu  = d_sumT1[i] * (1.f/NB);
    float var = d_sqT1[i] * (1.f/NB) - mu*mu;
    float aa  = tg1[i] * rsqrtf(var + 1e-5f);
    sA[i] = aa;
    sC[i] = tbt1[i] - mu*aa;
  }
  __syncthreads();
  int w = (blockIdx.x*blockDim.x + threadIdx.x) >> 5;
  int lane = threadIdx.x & 31;
  if(w >= NB) return;
  size_t b = (size_t)w;
  float v0a = fmaxf(d_t2raw[b*64 + lane]*sA[lane] + sC[lane], 0.f);
  float v0b = fmaxf(d_t2raw[b*64 + lane + 32]*sA[lane + 32] + sC[lane + 32], 0.f);
  float v1a = fmaxf(d_t2raw[(size_t)NB*64 + b*64 + lane]*sA[64 + lane] + sC[64 + lane], 0.f);
  float v1b = fmaxf(d_t2raw[(size_t)NB*64 + b*64 + lane + 32]*sA[64 + lane + 32] + sC[64 + lane + 32], 0.f);
  float s0 = v0a*tow[lane] + v0b*tow[lane + 32];
  float s1 = v1a*tow[64 + lane] + v1b*tow[64 + lane + 32];
  #pragma unroll
  for(int off=16; off; off>>=1){
    s0 += __shfl_xor_sync(0xffffffffu, s0, off);
    s1 += __shfl_xor_sync(0xffffffffu, s1, off);
  }
  if(lane==0){
    out[b]      = 1.f/(1.f + expf(-(s0 + tob[0])));
    out[NB + b] = 1.f/(1.f + expf(-(s1 + tob[1])));
  }
}

// ---------------- host launcher ----------------
extern "C" void kernel_launch(void* const* d_in, const int* in_sizes, int n_in,
                              void* d_out, int out_size){
  const int*   x    = (const int*)  d_in[0];
  const float* emb  = (const float*)d_in[1];
  const float* ew0  = (const float*)d_in[2];
  const float* eg0  = (const float*)d_in[4];
  const float* ebt0 = (const float*)d_in[5];
  const float* gw0  = (const float*)d_in[6];
  const float* gb0  = (const float*)d_in[7];
  const float* ew1  = (const float*)d_in[10];
  const float* eg1  = (const float*)d_in[12];
  const float* ebt1 = (const float*)d_in[13];
  const float* gw1  = (const float*)d_in[14];
  const float* gb1  = (const float*)d_in[15];
  const float* tw0  = (const float*)d_in[18];
  const float* tg0  = (const float*)d_in[20];
  const float* tbt0 = (const float*)d_in[21];
  const float* tw1  = (const float*)d_in[22];
  const float* tg1  = (const float*)d_in[24];
  const float* tbt1 = (const float*)d_in[25];
  const float* tow  = (const float*)d_in[26];
  const float* tob  = (const float*)d_in[27];
  float* out = (float*)d_out;

  static bool init_done = false;
  static cudaStream_t s1 = nullptr;
  static cudaEvent_t evRoot, evConv, evG, evGate0, evC0, evGate1;
  if(!init_done){
    cudaFuncSetAttribute(bf16_gemm_kernel<0>, cudaFuncAttributeMaxDynamicSharedMemorySize, SMEM_GB);
    cudaFuncSetAttribute(bf16_gemm_kernel<1>, cudaFuncAttributeMaxDynamicSharedMemorySize, SMEM_GB);
    cudaFuncSetAttribute(bf16_gemm_kernel<2>, cudaFuncAttributeMaxDynamicSharedMemorySize, SMEM_GB);
    cudaFuncSetAttribute(bf16_gemm_kernel<3>, cudaFuncAttributeMaxDynamicSharedMemorySize, SMEM_GB);
    cudaStreamCreateWithFlags(&s1, cudaStreamNonBlocking);
    cudaEventCreateWithFlags(&evRoot,  cudaEventDisableTiming);
    cudaEventCreateWithFlags(&evConv,  cudaEventDisableTiming);
    cudaEventCreateWithFlags(&evG,     cudaEventDisableTiming);
    cudaEventCreateWithFlags(&evGate0, cudaEventDisableTiming);
    cudaEventCreateWithFlags(&evC0,    cudaEventDisableTiming);
    cudaEventCreateWithFlags(&evGate1, cudaEventDisableTiming);
    init_done = true;
  }

  __nv_bfloat16* w0b;  cudaGetSymbolAddress((void**)&w0b,  d_w0b);
  __nv_bfloat16* w1b;  cudaGetSymbolAddress((void**)&w1b,  d_w1b);
  __nv_bfloat16* tw0b; cudaGetSymbolAddress((void**)&tw0b, d_tw0b);
  __nv_bfloat16* tw1b; cudaGetSymbolAddress((void**)&tw1b, d_tw1b);

  // fork side stream from capture stream
  cudaEventRecord(evRoot, 0);
  cudaStreamWaitEvent(s1, evRoot, 0);

  // s1: zero stats + all weight conversions (independent of gather)
  zero_stats_kernel<<<(12*D1 + 255)/256, 256, 0, s1>>>();
  conv_bf16_kernel<<<(12*IN0*D1/4 + 255)/256, 256, 0, s1>>>(ew0, w0b, 12*IN0*D1/4);
  conv_bf16_kernel<<<(12*D1*D2/4 + 255)/256, 256, 0, s1>>>(ew1, w1b, 12*D1*D2/4);
  conv_bf16_kernel<<<(2*D2*128/4 + 255)/256, 256, 0, s1>>>(tw0, tw0b, 2*D2*128/4);
  conv_bf16_kernel<<<(2*128*64/4 + 255)/256, 256, 0, s1>>>(tw1, tw1b, 2*128*64/4);
  cudaEventRecord(evConv, s1);

  // s0: gather
  gather_kernel<<<(NB*NF*16)/256, 256>>>(x, emb);
  cudaEventRecord(evG, 0);

  // s1: gate0 (needs gather) — overlaps GEMM0 on s0
  cudaStreamWaitEvent(s1, evG, 0);
  gate0_kernel<<<(NB*32)/256, 256, 0, s1>>>(gw0, gb0);
  cudaEventRecord(evGate0, s1);

  // s0: GEMM0 (needs conv + zero)
  cudaStreamWaitEvent(0, evConv, 0);
  bf16_gemm_kernel<0><<<dim3(D1/128, NB/BM, 12), 128, SMEM_GB>>>(w0b, w1b);
  finalize_kernel<<<(12*D1 + 255)/256, 256>>>(0, eg0, ebt0);
  cudaStreamWaitEvent(0, evGate0, 0);
  combine0_kernel<<<(NB*128)/256, 256>>>();
  cudaEventRecord(evC0, 0);

  // s1: gate1 (needs combine0) — overlaps GEMM1 on s0
  cudaStreamWaitEvent(s1, evC0, 0);
  gate1_kernel<<<(NB*32)/256, 256, 0, s1>>>(gw1, gb1);
  cudaEventRecord(evGate1, s1);

  // s0: GEMM1
  bf16_gemm_kernel<1><<<dim3(D2/128, NB/BM, 16), 128, SMEM_GB>>>(w0b, w1b);
  finalize_kernel<<<(16*D2 + 255)/256, 256>>>(1, eg1, ebt1);
  cudaStreamWaitEvent(0, evGate1, 0);
  combine1_kernel<<<(NB*64)/256, 256>>>();

  // towers on the bf16 wmma engine (tower finalizes fused into consumers)
  bf16_gemm_kernel<2><<<dim3(1, NB/BM, 2), 128, SMEM_GB>>>(w0b, w1b);
  normrelu_b_kernel<<<(2*NB*32 + 255)/256, 256>>>(tg0, tbt0);
  bf16_gemm_kernel<3><<<dim3(1, NB/BM, 2), 128, SMEM_GB>>>(w0b, w1b);
  final_kernel<<<(NB*32)/256, 256>>>(tg1, tbt1, tow, tob, out);
}